// round 13
// baseline (speedup 1.0000x reference)
#include <cuda_runtime.h>
#include <cuda_fp16.h>
#include <cstdint>

// ---------------- problem constants ----------------
#define BB 8
#define NN 2048
#define CIN 64
#define NK 32
#define KDIM 4096
#define KD2  (KDIM/2)
#define NPTS (BB*NN)
#define COUT 128
#define TWO_PI 6.283185307179586f
#define NCHUNKS 4
#define CHPTS (NPTS / NCHUNKS)   // 4096 points per chunk

// ---------------- device scratch (static, no allocs) ----------------
__device__ __half   g_Ah[(size_t)NPTS * KDIM];      // [p][k] fp16
__device__ float    g_featT[(size_t)BB * NN * CIN]; // feature transposed [b][n][c]
__device__ float    g_xT[(size_t)BB * NN * 3];      // coords transposed [b][n][d]
__device__ unsigned g_cwP[(size_t)COUT * KD2];      // [o][k2] half2 packed along k
__device__ unsigned g_mwF[128 * 16];                // per-thread mma A-fragments of mw

// ---------------- host-side stream/event box (created pre-main; no device mem) ------
struct HxStreams {
    cudaStream_t s2;
    cudaEvent_t  evp[NCHUNKS];
    cudaEvent_t  evg;
    HxStreams() {
        cudaStreamCreateWithFlags(&s2, cudaStreamNonBlocking);
        for (int i = 0; i < NCHUNKS; i++)
            cudaEventCreateWithFlags(&evp[i], cudaEventDisableTiming);
        cudaEventCreateWithFlags(&evg, cudaEventDisableTiming);
    }
};
static HxStreams g_hx;

__device__ __forceinline__ unsigned pack2(float lo, float hi) {
    __half2 h = __floats2half2_rn(lo, hi);
    return *reinterpret_cast<unsigned*>(&h);
}

__device__ __forceinline__ void mma_f16(float& c0, float& c1, float& c2, float& c3,
                                        unsigned a0, unsigned a1, unsigned a2, unsigned a3,
                                        unsigned b0, unsigned b1) {
    asm volatile(
        "mma.sync.aligned.m16n8k16.row.col.f32.f16.f16.f32 "
        "{%0,%1,%2,%3},{%4,%5,%6,%7},{%8,%9},{%0,%1,%2,%3};"
        : "+f"(c0), "+f"(c1), "+f"(c2), "+f"(c3)
        : "r"(a0), "r"(a1), "r"(a2), "r"(a3), "r"(b0), "r"(b1));
}

__device__ __forceinline__ uint32_t smem_u32(const void* p) {
    uint32_t a;
    asm("{ .reg .u64 t; cvta.to.shared.u64 t, %1; cvt.u32.u64 %0, t; }" : "=r"(a) : "l"(p));
    return a;
}
__device__ __forceinline__ void cp16(uint32_t s, const void* g) {
    asm volatile("cp.async.cg.shared.global [%0], [%1], 16;" :: "r"(s), "l"(g));
}
__device__ __forceinline__ void cp_commit() {
    asm volatile("cp.async.commit_group;" ::: "memory");
}
template <int N>
__device__ __forceinline__ void cp_wait() {
    asm volatile("cp.async.wait_group %0;" :: "n"(N) : "memory");
}
__device__ __forceinline__ void ldsm4(unsigned& r0, unsigned& r1, unsigned& r2, unsigned& r3,
                                      uint32_t addr) {
    asm volatile("ldmatrix.sync.aligned.m8n8.x4.shared.b16 {%0,%1,%2,%3}, [%4];"
                 : "=r"(r0), "=r"(r1), "=r"(r2), "=r"(r3) : "r"(addr));
}

// ---------------- kernel 0: transposes + weight packing + mw fragments ----------------
__global__ void prep_kernel(const float* __restrict__ x,
                            const float* __restrict__ feat,
                            const float* __restrict__ cw,
                            const float* __restrict__ mw) {
    const int stride = gridDim.x * blockDim.x;
    const int tid = blockIdx.x * blockDim.x + threadIdx.x;

    for (int e = tid; e < 128 * 4; e += stride) {
        int t = e >> 2, ks = e & 3;
        int w = t >> 5, lane = t & 31;
        int grp = lane >> 2, tig = lane & 3;
        int r0 = w * 16 + grp;
        int m0 = ks * 16 + 2 * tig;
        g_mwF[t * 16 + ks * 4 + 0] = pack2(mw[r0 * 64 + m0],           mw[r0 * 64 + m0 + 1]);
        g_mwF[t * 16 + ks * 4 + 1] = pack2(mw[(r0 + 8) * 64 + m0],     mw[(r0 + 8) * 64 + m0 + 1]);
        g_mwF[t * 16 + ks * 4 + 2] = pack2(mw[r0 * 64 + m0 + 8],       mw[r0 * 64 + m0 + 9]);
        g_mwF[t * 16 + ks * 4 + 3] = pack2(mw[(r0 + 8) * 64 + m0 + 8], mw[(r0 + 8) * 64 + m0 + 9]);
    }
    for (int e = tid; e < BB * CIN * NN; e += stride) {
        int b = e / (CIN * NN);
        int r = e - b * (CIN * NN);
        int c = r / NN;
        int n = r - c * NN;
        g_featT[((size_t)b * NN + n) * CIN + c] = feat[e];
    }
    for (int e = tid; e < BB * 3 * NN; e += stride) {
        int b = e / (3 * NN);
        int r = e - b * (3 * NN);
        int d = r / NN;
        int n = r - d * NN;
        g_xT[((size_t)b * NN + n) * 3 + d] = x[e];
    }
    for (int e = tid; e < COUT * KD2; e += stride)
        g_cwP[e] = pack2(cw[2 * e], cw[2 * e + 1]);
}

// ---------------- kernel 1: 2 points per CTA (round-11 proven form) ----------
__global__ __launch_bounds__(256, 4) void point_kernel(
    int pbase,
    const int*   __restrict__ nidx,
    const float* __restrict__ Brff,   // [7,32]
    const float* __restrict__ kern,   // [3,32]
    const float* __restrict__ mb)     // [64]
{
    const int tc = threadIdx.x;        // 0..255
    const int wg = tc >> 7;            // point sub-id within CTA
    const int wt = tc & 127;           // thread within warpgroup
    const int p = pbase + blockIdx.x * 2 + wg;
    const int b = p >> 11;
    const int lane = wt & 31;
    const int w = wt >> 5;
    const int grp = lane >> 2;
    const int tig = lane & 3;

    __shared__ unsigned u_xf[2][32][36];
    __shared__ unsigned u_F[2][128][20];
    __shared__ unsigned u_pT[2][32][20];
    __shared__ float s_br[7][32];
    __shared__ float s_kn[3][32];
    __shared__ float s_base[2][32];
    __shared__ float s_rel[2][32][3];
    __shared__ float s_dis[2][32];
    __shared__ float s_red[2][4][32];
    __shared__ int   s_idx[2][32];

    unsigned amw[4][4];
    {
        const unsigned* fp = g_mwF + wt * 16;
        #pragma unroll
        for (int ks = 0; ks < 4; ks++) {
            uint4 v = *reinterpret_cast<const uint4*>(fp + ks * 4);
            amw[ks][0] = v.x; amw[ks][1] = v.y; amw[ks][2] = v.z; amw[ks][3] = v.w;
        }
    }
    const float bv0 = mb[w * 16 + grp];
    const float bv1 = mb[w * 16 + grp + 8];

    for (int e = tc; e < 224; e += 256) s_br[e >> 5][e & 31] = Brff[e] * TWO_PI;
    for (int e = tc; e < 96;  e += 256) s_kn[e >> 5][e & 31] = kern[e];
    if (wt < 32) s_idx[wg][wt] = nidx[p * NK + wt];
    __syncthreads();

    float cx = 0.f, cy = 0.f, cz = 0.f;
    if (wt < 32) {
        const float* cp = g_xT + ((size_t)b * NN + s_idx[wg][wt]) * 3;
        cx = cp[0]; cy = cp[1]; cz = cp[2];
    }

    #pragma unroll
    for (int it = 0; it < 8; it++) {
        int e = wt + it * 128;
        int c = e & 63, k2 = e >> 6;
        float f0 = g_featT[((size_t)b * NN + s_idx[wg][2 * k2])     * CIN + c];
        float f1 = g_featT[((size_t)b * NN + s_idx[wg][2 * k2 + 1]) * CIN + c];
        u_F[wg][(c & 31) * 4 + (c >> 5)][k2] = pack2(f0, f1);
    }

    if (wt < 32) {
        float c0x = __shfl_sync(0xffffffffu, cx, 0);
        float c0y = __shfl_sync(0xffffffffu, cy, 0);
        float c0z = __shfl_sync(0xffffffffu, cz, 0);
        float rx = cx - c0x, ry = cy - c0y, rz = cz - c0z;
        s_rel[wg][wt][0] = rx; s_rel[wg][wt][1] = ry; s_rel[wg][wt][2] = rz;
        s_dis[wg][wt] = sqrtf(rx * rx + ry * ry + rz * rz);
        s_base[wg][wt] = c0x * s_br[0][wt] + c0y * s_br[1][wt] + c0z * s_br[2][wt];
    }
    __syncthreads();

    #pragma unroll
    for (int it = 0; it < 4; it++) {
        int e = wt + it * 128;
        int k = e >> 4, m2 = e & 15;
        float rx = s_rel[wg][k][0], ry = s_rel[wg][k][1], rz = s_rel[wg][k][2];
        float dd = s_dis[wg][k];
        int m = 2 * m2;
        float t0 = s_base[wg][m]   + rx * s_br[3][m]   + ry * s_br[4][m]
                 + rz * s_br[5][m]   + dd * s_br[6][m];
        float t1 = s_base[wg][m+1] + rx * s_br[3][m+1] + ry * s_br[4][m+1]
                 + rz * s_br[5][m+1] + dd * s_br[6][m+1];
        float s0, cv0, s1, cv1;
        __sincosf(t0, &s0, &cv0);
        __sincosf(t1, &s1, &cv1);
        u_xf[wg][k][m2]      = pack2(s0, s1);
        u_xf[wg][k][16 + m2] = pack2(cv0, cv1);
    }

    {
        const int j = wt & 31;
        const int q = wt >> 5;
        const float kx = s_kn[0][j], ky = s_kn[1][j], kz = s_kn[2][j];
        float d[8];
        float ps1 = 0.f;
        #pragma unroll
        for (int r = 0; r < 8; r++) {
            const int i = q * 8 + r;
            float v = s_rel[wg][i][0] * kx + s_rel[wg][i][1] * ky + s_rel[wg][i][2] * kz;
            if (i == 0 && j == 0) v += 1.0f;
            v = fmaxf(v, 0.f);
            d[r] = v;
            ps1 += v;
        }
        s_red[wg][q][j] = ps1;
        __syncthreads();
        float s1t = s_red[wg][0][j] + s_red[wg][1][j] + s_red[wg][2][j] + s_red[wg][3][j];
        float r1 = 1.0f / (s1t + 1e-6f);
        float ps2 = 0.f;
        #pragma unroll
        for (int r = 0; r < 8; r++) {
            float v = d[r] * r1;
            d[r] = v;
            ps2 += v * v;
        }
        __syncthreads();
        s_red[wg][q][j] = ps2;
        __syncthreads();
        float s2t = s_red[wg][0][j] + s_red[wg][1][j] + s_red[wg][2][j] + s_red[wg][3][j];
        float r2 = 1.0f / (s2t + 1e-6f);
        #pragma unroll
        for (int rp = 0; rp < 4; rp++) {
            float v0 = d[2 * rp]     * d[2 * rp]     * r2;
            float v1 = d[2 * rp + 1] * d[2 * rp + 1] * r2;
            v0 = (v0 > 0.1f) ? v0 : 0.0f;
            v1 = (v1 > 0.1f) ? v1 : 0.0f;
            u_pT[wg][j][4 * q + rp] = pack2(v0, v1);
        }
    }
    __syncthreads();

    {
        float acc[4][4];
        #pragma unroll
        for (int nt = 0; nt < 4; nt++) {
            acc[nt][0] = bv0; acc[nt][1] = bv0;
            acc[nt][2] = bv1; acc[nt][3] = bv1;
        }
        #pragma unroll
        for (int ks = 0; ks < 4; ks++) {
            const int kb = ks * 8;
            #pragma unroll
            for (int nt = 0; nt < 4; nt++) {
                unsigned b0 = u_xf[wg][nt * 8 + grp][kb + tig];
                unsigned b1 = u_xf[wg][nt * 8 + grp][kb + tig + 4];
                mma_f16(acc[nt][0], acc[nt][1], acc[nt][2], acc[nt][3],
                        amw[ks][0], amw[ks][1], amw[ks][2], amw[ks][3], b0, b1);
            }
        }
        const int r0 = w * 16 + grp, r1 = r0 + 8;
        const int cs0 = (r0 & 31) * 4 + 2 + (r0 >> 5);
        const int cs1 = (r1 & 31) * 4 + 2 + (r1 >> 5);
        #pragma unroll
        for (int nt = 0; nt < 4; nt++) {
            u_F[wg][cs0][nt * 4 + tig] = pack2(acc[nt][0], acc[nt][1]);
            u_F[wg][cs1][nt * 4 + tig] = pack2(acc[nt][2], acc[nt][3]);
        }
    }
    __syncthreads();

    {
        float acc[2][4][4];
        #pragma unroll
        for (int mt = 0; mt < 2; mt++)
            #pragma unroll
            for (int nt = 0; nt < 4; nt++)
                #pragma unroll
                for (int r = 0; r < 4; r++) acc[mt][nt][r] = 0.f;

        #pragma unroll
        for (int ks = 0; ks < 2; ks++) {
            const int kb = ks * 8;
            unsigned a[2][4];
            #pragma unroll
            for (int mt = 0; mt < 2; mt++) {
                const int rb = w * 32 + mt * 16;
                a[mt][0] = u_F[wg][rb + grp][kb + tig];
                a[mt][1] = u_F[wg][rb + grp + 8][kb + tig];
                a[mt][2] = u_F[wg][rb + grp][kb + tig + 4];
                a[mt][3] = u_F[wg][rb + grp + 8][kb + tig + 4];
            }
            #pragma unroll
            for (int nt = 0; nt < 4; nt++) {
                unsigned b0 = u_pT[wg][nt * 8 + grp][kb + tig];
                unsigned b1 = u_pT[wg][nt * 8 + grp][kb + tig + 4];
                #pragma unroll
                for (int mt = 0; mt < 2; mt++)
                    mma_f16(acc[mt][nt][0], acc[mt][nt][1], acc[mt][nt][2], acc[mt][nt][3],
                            a[mt][0], a[mt][1], a[mt][2], a[mt][3], b0, b1);
            }
        }

        // stage back into u_F in [row][k2] layout (warp overwrites only its own rows)
        #pragma unroll
        for (int mt = 0; mt < 2; mt++) {
            const int r = w * 32 + mt * 16 + grp;
            #pragma unroll
            for (int nt = 0; nt < 4; nt++) {
                u_F[wg][r][nt * 4 + tig]     = pack2(acc[mt][nt][0], acc[mt][nt][1]);
                u_F[wg][r + 8][nt * 4 + tig] = pack2(acc[mt][nt][2], acc[mt][nt][3]);
            }
        }
    }
    __syncthreads();

    // coalesced copy-out: u_F[wg] -> g_Ah[p]
    {
        unsigned* Ap = reinterpret_cast<unsigned*>(g_Ah + (size_t)p * KDIM);
        #pragma unroll
        for (int it = 0; it < 4; it++) {
            int e = wt + it * 128;
            int row = e >> 2;
            int c4 = (e & 3) * 4;
            uint4 v = *reinterpret_cast<const uint4*>(&u_F[wg][row][c4]);
            *reinterpret_cast<uint4*>(Ap + row * 16 + c4) = v;
        }
    }
}

// ---------------- kernel 2: M-split gemm — 64m x 128n tiles, cp.async 4-stage ------
#define ROW_U 20
#define TM 64
#define A_ST_U (TM * ROW_U)
#define B_ST_U (128 * ROW_U)
#define STAGE_U (A_ST_U + B_ST_U)
#define NSTAGE 4
#define G_SMEM (NSTAGE * STAGE_U * 4)   // 61440 B
#define NIT 128

__global__ __launch_bounds__(256, 2) void gemm_kernel(
    int pbase, const float* __restrict__ bias, float* __restrict__ out)
{
    extern __shared__ unsigned sm[];
    __shared__ float s_bias[COUT];

    const int t = threadIdx.x;
    const int p0 = pbase + blockIdx.x * TM;
    const int bb = p0 >> 11;
    const int n0 = p0 & (NN - 1);

    if (t < COUT) s_bias[t] = bias[t];

    const int lane = t & 31;
    const int wid  = t >> 5;
    const int grp  = lane >> 2;
    const int tig  = lane & 3;
    const int wm = (wid & 1) * 32;
    const int wn = (wid >> 1) * 32;

    const unsigned* Ag = reinterpret_cast<const unsigned*>(g_Ah);
    const unsigned* Bg = g_cwP;
    const uint32_t smb = smem_u32(sm);

    const int srow = t >> 2;
    const int sch  = t & 3;

    auto issue = [&](int q, int slot) {
        const uint32_t sb = smb + slot * (STAGE_U * 4);
        cp16(sb + srow * 80 + sch * 16,
             Ag + (size_t)(p0 + srow) * KD2 + q * 16 + sch * 4);
        #pragma unroll
        for (int i = 0; i < 2; i++) {
            int o = srow + 64 * i;
            cp16(sb + A_ST_U * 4 + o * 80 + sch * 16,
                 Bg + (size_t)o * KD2 + q * 16 + sch * 4);
        }
        cp_commit();
    };

    float c[2][4][4];
    #pragma unroll
    for (int ma = 0; ma < 2; ma++)
        #pragma unroll
        for (int nb = 0; nb < 4; nb++)
            #pragma unroll
            for (int r = 0; r < 4; r++) c[ma][nb][r] = 0.f;

    issue(0, 0);
    issue(1, 1);
    issue(2, 2);

    const int lrow8 = lane & 7;
    const int lhi   = (lane >> 3) & 1;
    const int lcol  = (lane >> 4) & 1;

    for (int i = 0; i < NIT; i++) {
        cp_wait<2>();
        __syncthreads();
        if (i + 3 < NIT) issue(i + 3, (i + 3) & 3);

        const uint32_t ab = smb + (i & 3) * (STAGE_U * 4);
        const uint32_t bbod = ab + A_ST_U * 4;

        unsigned a[2][2][4];
        #pragma unroll
        for (int ks = 0; ks < 2; ks++)
            #pragma unroll
            for (int ma = 0; ma < 2; ma++) {
                int row = wm + ma * 16 + lrow8 + lhi * 8;
                uint32_t addr = ab + row * 80 + ks * 32 + lcol * 16;
                ldsm4(a[ks][ma][0], a[ks][ma][1], a[ks][ma][2], a[ks][ma][3], addr);
            }
        unsigned bf[4][4];
        {
            const int bcol = (lane >> 3) * 16;
            #pragma unroll
            for (int nb = 0; nb < 4; nb++) {
                int row = wn + nb * 8 + lrow8;
                ldsm4(bf[nb][0], bf[nb][1], bf[nb][2], bf[nb][3],
                      bbod + row * 80 + bcol);
            }
        }
        #pragma unroll
        for (int ks = 0; ks < 2; ks++)
            #pragma unroll
            for (int nb = 0; nb < 4; nb++)
                #pragma unroll
                for (int ma = 0; ma < 2; ma++)
                    mma_f16(c[ma][nb][0], c[ma][nb][1], c[ma][nb][2], c[ma][nb][3],
                            a[ks][ma][0], a[ks][ma][1], a[ks][ma][2], a[ks][ma][3],
                            bf[nb][2 * ks], bf[nb][2 * ks + 1]);
    }

    float* ob = out + (size_t)bb * COUT * NN;
    #pragma unroll
    for (int ma = 0; ma < 2; ma++) {
        const int m0 = wm + ma * 16 + grp;
        #pragma unroll
        for (int nb = 0; nb < 4; nb++) {
            const int col0 = wn + nb * 8 + tig * 2;
            const float bv0 = s_bias[col0], bv1 = s_bias[col0 + 1];
            ob[(size_t)col0       * NN + n0 + m0]     = c[ma][nb][0] + bv0;
            ob[(size_t)(col0 + 1) * NN + n0 + m0]     = c[ma][nb][1] + bv1;
            ob[(size_t)col0       * NN + n0 + m0 + 8] = c[ma][nb][2] + bv0;
            ob[(size_t)(col0 + 1) * NN + n0 + m0 + 8] = c[ma][nb][3] + bv1;
        }
    }
}

// ---------------- launch: chunked dual-stream overlap ----------------
extern "C" void kernel_launch(void* const* d_in, const int* in_sizes, int n_in,
                              void* d_out, int out_size) {
    const float* x       = (const float*)d_in[0];
    const float* feature = (const float*)d_in[1];
    const int*   nidx    = (const int*)  d_in[2];
    const float* Brff    = (const float*)d_in[3];
    const float* kern    = (const float*)d_in[4];
    const float* mw      = (const float*)d_in[5];
    const float* mb      = (const float*)d_in[6];
    const float* cw      = (const float*)d_in[7];
    const float* cb      = (const float*)d_in[8];
    float* out = (float*)d_out;

    cudaFuncSetAttribute(gemm_kernel,
                         cudaFuncAttributeMaxDynamicSharedMemorySize, G_SMEM);

    // prep on the capture (default) stream
    prep_kernel<<<1024, 256>>>(x, feature, cw, mw);

    // chunked pipeline: point chunk c on default stream; gemm chunk c on g_hx.s2
    // gated by an event after point chunk c. gemm chunks serialize among
    // themselves on s2; final join edge back to the default stream.
    for (int c = 0; c < NCHUNKS; c++) {
        point_kernel<<<CHPTS / 2, 256>>>(c * CHPTS, nidx, Brff, kern, mb);
        cudaEventRecord(g_hx.evp[c], 0);
        cudaStreamWaitEvent(g_hx.s2, g_hx.evp[c], 0);
        gemm_kernel<<<CHPTS / TM, 256, G_SMEM, g_hx.s2>>>(c * CHPTS, cb, out);
    }
    cudaEventRecord(g_hx.evg, g_hx.s2);
    cudaStreamWaitEvent(0, g_hx.evg, 0);
}

// round 14
// speedup vs baseline: 1.3969x; 1.3969x over previous
#include <cuda_runtime.h>
#include <cuda_fp16.h>
#include <cstdint>

// ---------------- problem constants ----------------
#define BB 8
#define NN 2048
#define CIN 64
#define NK 32
#define KDIM 4096
#define KD2  (KDIM/2)
#define NPTS (BB*NN)
#define COUT 128
#define TWO_PI 6.283185307179586f

// ---------------- device scratch (static, no allocs) ----------------
__device__ __half   g_Ah[(size_t)NPTS * KDIM];      // [p][k] fp16
__device__ float    g_featT[(size_t)BB * NN * CIN]; // feature transposed [b][n][c]
__device__ float    g_xT[(size_t)BB * NN * 3];      // coords transposed [b][n][d]
__device__ unsigned g_cwP[(size_t)COUT * KD2];      // [o][k2] half2 packed along k
__device__ unsigned g_mwF[128 * 16];                // per-thread mma A-fragments of mw

__device__ __forceinline__ unsigned pack2(float lo, float hi) {
    __half2 h = __floats2half2_rn(lo, hi);
    return *reinterpret_cast<unsigned*>(&h);
}

__device__ __forceinline__ void mma_f16(float& c0, float& c1, float& c2, float& c3,
                                        unsigned a0, unsigned a1, unsigned a2, unsigned a3,
                                        unsigned b0, unsigned b1) {
    asm volatile(
        "mma.sync.aligned.m16n8k16.row.col.f32.f16.f16.f32 "
        "{%0,%1,%2,%3},{%4,%5,%6,%7},{%8,%9},{%0,%1,%2,%3};"
        : "+f"(c0), "+f"(c1), "+f"(c2), "+f"(c3)
        : "r"(a0), "r"(a1), "r"(a2), "r"(a3), "r"(b0), "r"(b1));
}

__device__ __forceinline__ uint32_t smem_u32(const void* p) {
    uint32_t a;
    asm("{ .reg .u64 t; cvta.to.shared.u64 t, %1; cvt.u32.u64 %0, t; }" : "=r"(a) : "l"(p));
    return a;
}
__device__ __forceinline__ void cp16(uint32_t s, const void* g) {
    asm volatile("cp.async.cg.shared.global [%0], [%1], 16;" :: "r"(s), "l"(g));
}
__device__ __forceinline__ void cp_commit() {
    asm volatile("cp.async.commit_group;" ::: "memory");
}
template <int N>
__device__ __forceinline__ void cp_wait() {
    asm volatile("cp.async.wait_group %0;" :: "n"(N) : "memory");
}
__device__ __forceinline__ void ldsm4(unsigned& r0, unsigned& r1, unsigned& r2, unsigned& r3,
                                      uint32_t addr) {
    asm volatile("ldmatrix.sync.aligned.m8n8.x4.shared.b16 {%0,%1,%2,%3}, [%4];"
                 : "=r"(r0), "=r"(r1), "=r"(r2), "=r"(r3) : "r"(addr));
}

// ---------------- kernel 0: transposes + weight packing + mw fragments ----------------
__global__ void prep_kernel(const float* __restrict__ x,
                            const float* __restrict__ feat,
                            const float* __restrict__ cw,
                            const float* __restrict__ mw) {
    const int stride = gridDim.x * blockDim.x;
    const int tid = blockIdx.x * blockDim.x + threadIdx.x;

    for (int e = tid; e < 128 * 4; e += stride) {
        int t = e >> 2, ks = e & 3;
        int w = t >> 5, lane = t & 31;
        int grp = lane >> 2, tig = lane & 3;
        int r0 = w * 16 + grp;
        int m0 = ks * 16 + 2 * tig;
        g_mwF[t * 16 + ks * 4 + 0] = pack2(mw[r0 * 64 + m0],           mw[r0 * 64 + m0 + 1]);
        g_mwF[t * 16 + ks * 4 + 1] = pack2(mw[(r0 + 8) * 64 + m0],     mw[(r0 + 8) * 64 + m0 + 1]);
        g_mwF[t * 16 + ks * 4 + 2] = pack2(mw[r0 * 64 + m0 + 8],       mw[r0 * 64 + m0 + 9]);
        g_mwF[t * 16 + ks * 4 + 3] = pack2(mw[(r0 + 8) * 64 + m0 + 8], mw[(r0 + 8) * 64 + m0 + 9]);
    }
    for (int e = tid; e < BB * CIN * NN; e += stride) {
        int b = e / (CIN * NN);
        int r = e - b * (CIN * NN);
        int c = r / NN;
        int n = r - c * NN;
        g_featT[((size_t)b * NN + n) * CIN + c] = feat[e];
    }
    for (int e = tid; e < BB * 3 * NN; e += stride) {
        int b = e / (3 * NN);
        int r = e - b * (3 * NN);
        int d = r / NN;
        int n = r - d * NN;
        g_xT[((size_t)b * NN + n) * 3 + d] = x[e];
    }
    for (int e = tid; e < COUT * KD2; e += stride)
        g_cwP[e] = pack2(cw[2 * e], cw[2 * e + 1]);
}

// ---------------- kernel 1: 2 points per CTA, ldmatrix fragment loads ----------
__global__ __launch_bounds__(256, 4) void point_kernel(
    const int*   __restrict__ nidx,
    const float* __restrict__ Brff,   // [7,32]
    const float* __restrict__ kern,   // [3,32]
    const float* __restrict__ mb)     // [64]
{
    const int tc = threadIdx.x;        // 0..255
    const int wg = tc >> 7;            // point sub-id within CTA
    const int wt = tc & 127;           // thread within warpgroup
    const int p = blockIdx.x * 2 + wg;
    const int b = p >> 11;
    const int lane = wt & 31;
    const int w = wt >> 5;
    const int grp = lane >> 2;
    const int tig = lane & 3;
    const int lrow8 = lane & 7;
    const int lhi   = (lane >> 3) & 1;
    const int lcol  = (lane >> 4) & 1;
    const int l3    = lane >> 3;       // 0..3

    __shared__ unsigned u_xf[2][32][36];   // pitch 144B (16B-multiple)
    __shared__ unsigned u_F[2][128][20];   // pitch 80B
    __shared__ unsigned u_pT[2][32][20];   // pitch 80B
    __shared__ float s_br[7][32];
    __shared__ float s_kn[3][32];
    __shared__ float s_base[2][32];
    __shared__ float s_rel[2][32][3];
    __shared__ float s_dis[2][32];
    __shared__ float s_red[2][4][32];
    __shared__ int   s_idx[2][32];

    const uint32_t xfb = smem_u32(&u_xf[wg][0][0]);
    const uint32_t fb  = smem_u32(&u_F[wg][0][0]);
    const uint32_t ptb = smem_u32(&u_pT[wg][0][0]);

    unsigned amw[4][4];
    {
        const unsigned* fp = g_mwF + wt * 16;
        #pragma unroll
        for (int ks = 0; ks < 4; ks++) {
            uint4 v = *reinterpret_cast<const uint4*>(fp + ks * 4);
            amw[ks][0] = v.x; amw[ks][1] = v.y; amw[ks][2] = v.z; amw[ks][3] = v.w;
        }
    }
    const float bv0 = mb[w * 16 + grp];
    const float bv1 = mb[w * 16 + grp + 8];

    for (int e = tc; e < 224; e += 256) s_br[e >> 5][e & 31] = Brff[e] * TWO_PI;
    for (int e = tc; e < 96;  e += 256) s_kn[e >> 5][e & 31] = kern[e];
    if (wt < 32) s_idx[wg][wt] = nidx[p * NK + wt];
    __syncthreads();

    float cx = 0.f, cy = 0.f, cz = 0.f;
    if (wt < 32) {
        const float* cp = g_xT + ((size_t)b * NN + s_idx[wg][wt]) * 3;
        cx = cp[0]; cy = cp[1]; cz = cp[2];
    }

    // feature gather -> u_F (shuffled rows 0,1 mod 4), packed neighbor pairs
    #pragma unroll
    for (int it = 0; it < 8; it++) {
        int e = wt + it * 128;
        int c = e & 63, k2 = e >> 6;
        float f0 = g_featT[((size_t)b * NN + s_idx[wg][2 * k2])     * CIN + c];
        float f1 = g_featT[((size_t)b * NN + s_idx[wg][2 * k2 + 1]) * CIN + c];
        u_F[wg][(c & 31) * 4 + (c >> 5)][k2] = pack2(f0, f1);
    }

    if (wt < 32) {
        float c0x = __shfl_sync(0xffffffffu, cx, 0);
        float c0y = __shfl_sync(0xffffffffu, cy, 0);
        float c0z = __shfl_sync(0xffffffffu, cz, 0);
        float rx = cx - c0x, ry = cy - c0y, rz = cz - c0z;
        s_rel[wg][wt][0] = rx; s_rel[wg][wt][1] = ry; s_rel[wg][wt][2] = rz;
        s_dis[wg][wt] = sqrtf(rx * rx + ry * ry + rz * rz);
        s_base[wg][wt] = c0x * s_br[0][wt] + c0y * s_br[1][wt] + c0z * s_br[2][wt];
    }
    __syncthreads();

    // ---- RFF: sin/cos pairs -> u_xf ----
    #pragma unroll
    for (int it = 0; it < 4; it++) {
        int e = wt + it * 128;
        int k = e >> 4, m2 = e & 15;
        float rx = s_rel[wg][k][0], ry = s_rel[wg][k][1], rz = s_rel[wg][k][2];
        float dd = s_dis[wg][k];
        int m = 2 * m2;
        float t0 = s_base[wg][m]   + rx * s_br[3][m]   + ry * s_br[4][m]
                 + rz * s_br[5][m]   + dd * s_br[6][m];
        float t1 = s_base[wg][m+1] + rx * s_br[3][m+1] + ry * s_br[4][m+1]
                 + rz * s_br[5][m+1] + dd * s_br[6][m+1];
        float s0, cv0, s1, cv1;
        __sincosf(t0, &s0, &cv0);
        __sincosf(t1, &s1, &cv1);
        u_xf[wg][k][m2]      = pack2(s0, s1);
        u_xf[wg][k][16 + m2] = pack2(cv0, cv1);
    }

    // ---- topkmax: parallel over 128 threads (col j, row-quarter q), dots in regs ----
    {
        const int j = wt & 31;
        const int q = wt >> 5;
        const float kx = s_kn[0][j], ky = s_kn[1][j], kz = s_kn[2][j];
        float d[8];
        float ps1 = 0.f;
        #pragma unroll
        for (int r = 0; r < 8; r++) {
            const int i = q * 8 + r;
            float v = s_rel[wg][i][0] * kx + s_rel[wg][i][1] * ky + s_rel[wg][i][2] * kz;
            if (i == 0 && j == 0) v += 1.0f;
            v = fmaxf(v, 0.f);
            d[r] = v;
            ps1 += v;
        }
        s_red[wg][q][j] = ps1;
        __syncthreads();
        float s1t = s_red[wg][0][j] + s_red[wg][1][j] + s_red[wg][2][j] + s_red[wg][3][j];
        float r1 = 1.0f / (s1t + 1e-6f);
        float ps2 = 0.f;
        #pragma unroll
        for (int r = 0; r < 8; r++) {
            float v = d[r] * r1;
            d[r] = v;
            ps2 += v * v;
        }
        __syncthreads();
        s_red[wg][q][j] = ps2;
        __syncthreads();
        float s2t = s_red[wg][0][j] + s_red[wg][1][j] + s_red[wg][2][j] + s_red[wg][3][j];
        float r2 = 1.0f / (s2t + 1e-6f);
        #pragma unroll
        for (int rp = 0; rp < 4; rp++) {
            float v0 = d[2 * rp]     * d[2 * rp]     * r2;
            float v1 = d[2 * rp + 1] * d[2 * rp + 1] * r2;
            v0 = (v0 > 0.1f) ? v0 : 0.0f;
            v1 = (v1 > 0.1f) ? v1 : 0.0f;
            u_pT[wg][j][4 * q + rp] = pack2(v0, v1);
        }
    }
    __syncthreads();

    // ---- GEMM1: mlp out rows [16w,16w+16), B fragments via ldmatrix ----
    {
        float acc[4][4];
        #pragma unroll
        for (int nt = 0; nt < 4; nt++) {
            acc[nt][0] = bv0; acc[nt][1] = bv0;
            acc[nt][2] = bv1; acc[nt][3] = bv1;
        }
        #pragma unroll
        for (int nt = 0; nt < 4; nt++) {
            unsigned bx[2][4];
            #pragma unroll
            for (int win = 0; win < 2; win++)
                ldsm4(bx[win][0], bx[win][1], bx[win][2], bx[win][3],
                      xfb + (nt * 8 + lrow8) * 144 + win * 64 + l3 * 16);
            #pragma unroll
            for (int ks = 0; ks < 4; ks++)
                mma_f16(acc[nt][0], acc[nt][1], acc[nt][2], acc[nt][3],
                        amw[ks][0], amw[ks][1], amw[ks][2], amw[ks][3],
                        bx[ks >> 1][(ks & 1) * 2], bx[ks >> 1][(ks & 1) * 2 + 1]);
        }
        const int r0 = w * 16 + grp, r1 = r0 + 8;
        const int cs0 = (r0 & 31) * 4 + 2 + (r0 >> 5);
        const int cs1 = (r1 & 31) * 4 + 2 + (r1 >> 5);
        #pragma unroll
        for (int nt = 0; nt < 4; nt++) {
            u_F[wg][cs0][nt * 4 + tig] = pack2(acc[nt][0], acc[nt][1]);
            u_F[wg][cs1][nt * 4 + tig] = pack2(acc[nt][2], acc[nt][3]);
        }
    }
    __syncthreads();

    // ---- GEMM2: feats2 = F @ perm, A/B fragments via ldmatrix ----
    {
        float acc[2][4][4];
        #pragma unroll
        for (int mt = 0; mt < 2; mt++)
            #pragma unroll
            for (int nt = 0; nt < 4; nt++)
                #pragma unroll
                for (int r = 0; r < 4; r++) acc[mt][nt][r] = 0.f;

        // A fragments: a[ks][mt][0..3]
        unsigned a[2][2][4];
        #pragma unroll
        for (int ks = 0; ks < 2; ks++)
            #pragma unroll
            for (int mt = 0; mt < 2; mt++) {
                int row = w * 32 + mt * 16 + lrow8 + lhi * 8;
                ldsm4(a[ks][mt][0], a[ks][mt][1], a[ks][mt][2], a[ks][mt][3],
                      fb + row * 80 + ks * 32 + lcol * 16);
            }
        // B fragments: bp[nt][0..3] = {b0ks0, b1ks0, b0ks1, b1ks1}
        unsigned bp[4][4];
        #pragma unroll
        for (int nt = 0; nt < 4; nt++)
            ldsm4(bp[nt][0], bp[nt][1], bp[nt][2], bp[nt][3],
                  ptb + (nt * 8 + lrow8) * 80 + l3 * 16);

        #pragma unroll
        for (int ks = 0; ks < 2; ks++)
            #pragma unroll
            for (int nt = 0; nt < 4; nt++)
                #pragma unroll
                for (int mt = 0; mt < 2; mt++)
                    mma_f16(acc[mt][nt][0], acc[mt][nt][1], acc[mt][nt][2], acc[mt][nt][3],
                            a[ks][mt][0], a[ks][mt][1], a[ks][mt][2], a[ks][mt][3],
                            bp[nt][2 * ks], bp[nt][2 * ks + 1]);

        // stage back into u_F in [row][k2] layout (warp overwrites only its own rows)
        #pragma unroll
        for (int mt = 0; mt < 2; mt++) {
            const int r = w * 32 + mt * 16 + grp;
            #pragma unroll
            for (int nt = 0; nt < 4; nt++) {
                u_F[wg][r][nt * 4 + tig]     = pack2(acc[mt][nt][0], acc[mt][nt][1]);
                u_F[wg][r + 8][nt * 4 + tig] = pack2(acc[mt][nt][2], acc[mt][nt][3]);
            }
        }
    }
    __syncthreads();

    // ---- coalesced copy-out: u_F[wg] -> g_Ah[p] ----
    {
        unsigned* Ap = reinterpret_cast<unsigned*>(g_Ah + (size_t)p * KDIM);
        #pragma unroll
        for (int it = 0; it < 4; it++) {
            int e = wt + it * 128;
            int row = e >> 2;
            int c4 = (e & 3) * 4;
            uint4 v = *reinterpret_cast<const uint4*>(&u_F[wg][row][c4]);
            *reinterpret_cast<uint4*>(Ap + row * 16 + c4) = v;
        }
    }
}

// ---------------- kernel 2: M-split gemm — 256 CTAs of 64m x 128n, cp.async 4-stage --
#define ROW_U 20
#define TM 64
#define A_ST_U (TM * ROW_U)
#define B_ST_U (128 * ROW_U)
#define STAGE_U (A_ST_U + B_ST_U)
#define NSTAGE 4
#define G_SMEM (NSTAGE * STAGE_U * 4)   // 61440 B
#define NIT 128

__global__ __launch_bounds__(256, 2) void gemm_kernel(
    const float* __restrict__ bias, float* __restrict__ out)
{
    extern __shared__ unsigned sm[];
    __shared__ float s_bias[COUT];

    const int t = threadIdx.x;
    const int p0 = blockIdx.x * TM;
    const int bb = p0 >> 11;
    const int n0 = p0 & (NN - 1);

    if (t < COUT) s_bias[t] = bias[t];

    const int lane = t & 31;
    const int wid  = t >> 5;
    const int grp  = lane >> 2;
    const int tig  = lane & 3;
    const int wm = (wid & 1) * 32;
    const int wn = (wid >> 1) * 32;

    const unsigned* Ag = reinterpret_cast<const unsigned*>(g_Ah);
    const unsigned* Bg = g_cwP;
    const uint32_t smb = smem_u32(sm);

    const int srow = t >> 2;
    const int sch  = t & 3;

    auto issue = [&](int q, int slot) {
        const uint32_t sb = smb + slot * (STAGE_U * 4);
        cp16(sb + srow * 80 + sch * 16,
             Ag + (size_t)(p0 + srow) * KD2 + q * 16 + sch * 4);
        #pragma unroll
        for (int i = 0; i < 2; i++) {
            int o = srow + 64 * i;
            cp16(sb + A_ST_U * 4 + o * 80 + sch * 16,
                 Bg + (size_t)o * KD2 + q * 16 + sch * 4);
        }
        cp_commit();
    };

    float c[2][4][4];
    #pragma unroll
    for (int ma = 0; ma < 2; ma++)
        #pragma unroll
        for (int nb = 0; nb < 4; nb++)
            #pragma unroll
            for (int r = 0; r < 4; r++) c[ma][nb][r] = 0.f;

    issue(0, 0);
    issue(1, 1);
    issue(2, 2);

    const int lrow8 = lane & 7;
    const int lhi   = (lane >> 3) & 1;
    const int lcol  = (lane >> 4) & 1;

    for (int i = 0; i < NIT; i++) {
        cp_wait<2>();
        __syncthreads();
        if (i + 3 < NIT) issue(i + 3, (i + 3) & 3);

        const uint32_t ab = smb + (i & 3) * (STAGE_U * 4);
        const uint32_t bbod = ab + A_ST_U * 4;

        unsigned a[2][2][4];
        #pragma unroll
        for (int ks = 0; ks < 2; ks++)
            #pragma unroll
            for (int ma = 0; ma < 2; ma++) {
                int row = wm + ma * 16 + lrow8 + lhi * 8;
                uint32_t addr = ab + row * 80 + ks * 32 + lcol * 16;
                ldsm4(a[ks][ma][0], a[ks][ma][1], a[ks][ma][2], a[ks][ma][3], addr);
            }
        unsigned bf[4][4];
        {
            const int bcol = (lane >> 3) * 16;
            #pragma unroll
            for (int nb = 0; nb < 4; nb++) {
                int row = wn + nb * 8 + lrow8;
                ldsm4(bf[nb][0], bf[nb][1], bf[nb][2], bf[nb][3],
                      bbod + row * 80 + bcol);
            }
        }
        #pragma unroll
        for (int ks = 0; ks < 2; ks++)
            #pragma unroll
            for (int nb = 0; nb < 4; nb++)
                #pragma unroll
                for (int ma = 0; ma < 2; ma++)
                    mma_f16(c[ma][nb][0], c[ma][nb][1], c[ma][nb][2], c[ma][nb][3],
                            a[ks][ma][0], a[ks][ma][1], a[ks][ma][2], a[ks][ma][3],
                            bf[nb][2 * ks], bf[nb][2 * ks + 1]);
    }

    float* ob = out + (size_t)bb * COUT * NN;
    #pragma unroll
    for (int ma = 0; ma < 2; ma++) {
        const int m0 = wm + ma * 16 + grp;
        #pragma unroll
        for (int nb = 0; nb < 4; nb++) {
            const int col0 = wn + nb * 8 + tig * 2;
            const float bv0 = s_bias[col0], bv1 = s_bias[col0 + 1];
            ob[(size_t)col0       * NN + n0 + m0]     = c[ma][nb][0] + bv0;
            ob[(size_t)(col0 + 1) * NN + n0 + m0]     = c[ma][nb][1] + bv1;
            ob[(size_t)col0       * NN + n0 + m0 + 8] = c[ma][nb][2] + bv0;
            ob[(size_t)(col0 + 1) * NN + n0 + m0 + 8] = c[ma][nb][3] + bv1;
        }
    }
}

// ---------------- launch ----------------
extern "C" void kernel_launch(void* const* d_in, const int* in_sizes, int n_in,
                              void* d_out, int out_size) {
    const float* x       = (const float*)d_in[0];
    const float* feature = (const float*)d_in[1];
    const int*   nidx    = (const int*)  d_in[2];
    const float* Brff    = (const float*)d_in[3];
    const float* kern    = (const float*)d_in[4];
    const float* mw      = (const float*)d_in[5];
    const float* mb      = (const float*)d_in[6];
    const float* cw      = (const float*)d_in[7];
    const float* cb      = (const float*)d_in[8];
    float* out = (float*)d_out;

    cudaFuncSetAttribute(gemm_kernel,
                         cudaFuncAttributeMaxDynamicSharedMemorySize, G_SMEM);

    prep_kernel<<<1024, 256>>>(x, feature, cw, mw);
    point_kernel<<<NPTS / 2, 256>>>(nidx, Brff, kern, mb);
    gemm_kernel<<<NPTS / TM, 256, G_SMEM>>>(cb, out);
}

// round 15
// speedup vs baseline: 1.4015x; 1.0033x over previous
#include <cuda_runtime.h>
#include <cuda_fp16.h>
#include <cstdint>

// ---------------- problem constants ----------------
#define BB 8
#define NN 2048
#define CIN 64
#define NK 32
#define KDIM 4096
#define KD2  (KDIM/2)
#define NPTS (BB*NN)
#define NPAIRS (NPTS/2)
#define COUT 128
#define TWO_PI 6.283185307179586f
#define PGRID 608   // 4 CTAs/SM x 152 SMs

// ---------------- device scratch (static, no allocs) ----------------
__device__ __half   g_Ah[(size_t)NPTS * KDIM];      // [p][k] fp16
__device__ float    g_featT[(size_t)BB * NN * CIN]; // feature transposed [b][n][c]
__device__ float    g_xT[(size_t)BB * NN * 3];      // coords transposed [b][n][d]
__device__ unsigned g_cwP[(size_t)COUT * KD2];      // [o][k2] half2 packed along k
__device__ unsigned g_mwF[128 * 16];                // per-thread mma A-fragments of mw

__device__ __forceinline__ unsigned pack2(float lo, float hi) {
    __half2 h = __floats2half2_rn(lo, hi);
    return *reinterpret_cast<unsigned*>(&h);
}

__device__ __forceinline__ void mma_f16(float& c0, float& c1, float& c2, float& c3,
                                        unsigned a0, unsigned a1, unsigned a2, unsigned a3,
                                        unsigned b0, unsigned b1) {
    asm volatile(
        "mma.sync.aligned.m16n8k16.row.col.f32.f16.f16.f32 "
        "{%0,%1,%2,%3},{%4,%5,%6,%7},{%8,%9},{%0,%1,%2,%3};"
        : "+f"(c0), "+f"(c1), "+f"(c2), "+f"(c3)
        : "r"(a0), "r"(a1), "r"(a2), "r"(a3), "r"(b0), "r"(b1));
}

__device__ __forceinline__ uint32_t smem_u32(const void* p) {
    uint32_t a;
    asm("{ .reg .u64 t; cvta.to.shared.u64 t, %1; cvt.u32.u64 %0, t; }" : "=r"(a) : "l"(p));
    return a;
}
__device__ __forceinline__ void cp16(uint32_t s, const void* g) {
    asm volatile("cp.async.cg.shared.global [%0], [%1], 16;" :: "r"(s), "l"(g));
}
__device__ __forceinline__ void cp_commit() {
    asm volatile("cp.async.commit_group;" ::: "memory");
}
template <int N>
__device__ __forceinline__ void cp_wait() {
    asm volatile("cp.async.wait_group %0;" :: "n"(N) : "memory");
}
__device__ __forceinline__ void ldsm4(unsigned& r0, unsigned& r1, unsigned& r2, unsigned& r3,
                                      uint32_t addr) {
    asm volatile("ldmatrix.sync.aligned.m8n8.x4.shared.b16 {%0,%1,%2,%3}, [%4];"
                 : "=r"(r0), "=r"(r1), "=r"(r2), "=r"(r3) : "r"(addr));
}

// ---------------- kernel 0: transposes + weight packing + mw fragments ----------------
__global__ void prep_kernel(const float* __restrict__ x,
                            const float* __restrict__ feat,
                            const float* __restrict__ cw,
                            const float* __restrict__ mw) {
    const int stride = gridDim.x * blockDim.x;
    const int tid = blockIdx.x * blockDim.x + threadIdx.x;

    for (int e = tid; e < 128 * 4; e += stride) {
        int t = e >> 2, ks = e & 3;
        int w = t >> 5, lane = t & 31;
        int grp = lane >> 2, tig = lane & 3;
        int r0 = w * 16 + grp;
        int m0 = ks * 16 + 2 * tig;
        g_mwF[t * 16 + ks * 4 + 0] = pack2(mw[r0 * 64 + m0],           mw[r0 * 64 + m0 + 1]);
        g_mwF[t * 16 + ks * 4 + 1] = pack2(mw[(r0 + 8) * 64 + m0],     mw[(r0 + 8) * 64 + m0 + 1]);
        g_mwF[t * 16 + ks * 4 + 2] = pack2(mw[r0 * 64 + m0 + 8],       mw[r0 * 64 + m0 + 9]);
        g_mwF[t * 16 + ks * 4 + 3] = pack2(mw[(r0 + 8) * 64 + m0 + 8], mw[(r0 + 8) * 64 + m0 + 9]);
    }
    for (int e = tid; e < BB * CIN * NN; e += stride) {
        int b = e / (CIN * NN);
        int r = e - b * (CIN * NN);
        int c = r / NN;
        int n = r - c * NN;
        g_featT[((size_t)b * NN + n) * CIN + c] = feat[e];
    }
    for (int e = tid; e < BB * 3 * NN; e += stride) {
        int b = e / (3 * NN);
        int r = e - b * (3 * NN);
        int d = r / NN;
        int n = r - d * NN;
        g_xT[((size_t)b * NN + n) * 3 + d] = x[e];
    }
    for (int e = tid; e < COUT * KD2; e += stride)
        g_cwP[e] = pack2(cw[2 * e], cw[2 * e + 1]);
}

// ---------------- kernel 1: PERSISTENT, 2 points per iteration, idx prefetch ---------
__global__ __launch_bounds__(256, 4) void point_kernel(
    const int*   __restrict__ nidx,
    const float* __restrict__ Brff,   // [7,32]
    const float* __restrict__ kern,   // [3,32]
    const float* __restrict__ mb)     // [64]
{
    const int tc = threadIdx.x;        // 0..255
    const int wg = tc >> 7;            // point sub-id within iteration
    const int wt = tc & 127;           // thread within warpgroup
    const int lane = wt & 31;
    const int w = wt >> 5;
    const int grp = lane >> 2;
    const int tig = lane & 3;
    const int lrow8 = lane & 7;
    const int lhi   = (lane >> 3) & 1;
    const int lcol  = (lane >> 4) & 1;
    const int l3    = lane >> 3;       // 0..3

    __shared__ unsigned u_xf[2][32][36];   // pitch 144B
    __shared__ unsigned u_F[2][128][20];   // pitch 80B
    __shared__ unsigned u_pT[2][32][20];   // pitch 80B
    __shared__ float s_br[7][32];
    __shared__ float s_kn[3][32];
    __shared__ float s_base[2][32];
    __shared__ float s_rel[2][32][3];
    __shared__ float s_dis[2][32];
    __shared__ float s_red[2][4][32];
    __shared__ int   s_idx2[2][2][32];     // [buf][wg][k]

    const uint32_t xfb = smem_u32(&u_xf[wg][0][0]);
    const uint32_t fb  = smem_u32(&u_F[wg][0][0]);
    const uint32_t ptb = smem_u32(&u_pT[wg][0][0]);

    // ---- hoisted constants (once per CTA) ----
    unsigned amw[4][4];
    {
        const unsigned* fp = g_mwF + wt * 16;
        #pragma unroll
        for (int ks = 0; ks < 4; ks++) {
            uint4 v = *reinterpret_cast<const uint4*>(fp + ks * 4);
            amw[ks][0] = v.x; amw[ks][1] = v.y; amw[ks][2] = v.z; amw[ks][3] = v.w;
        }
    }
    const float bv0 = mb[w * 16 + grp];
    const float bv1 = mb[w * 16 + grp + 8];

    for (int e = tc; e < 224; e += 256) s_br[e >> 5][e & 31] = Brff[e] * TWO_PI;
    for (int e = tc; e < 96;  e += 256) s_kn[e >> 5][e & 31] = kern[e];
    // preload idx for first pair
    if (wt < 32 && blockIdx.x < NPAIRS)
        s_idx2[0][wg][wt] = nidx[((size_t)blockIdx.x * 2 + wg) * NK + wt];
    __syncthreads();

    int buf = 0;
    for (int pi = blockIdx.x; pi < NPAIRS; pi += PGRID, buf ^= 1) {
        const int p = pi * 2 + wg;
        const int b = p >> 11;
        const int* idxc = s_idx2[buf][wg];

        // prefetch next pair's indices into the other buffer (visible after
        // this iteration's trailing __syncthreads)
        {
            int pin = pi + PGRID;
            if (pin < NPAIRS && wt < 32)
                s_idx2[buf ^ 1][wg][wt] = nidx[((size_t)pin * 2 + wg) * NK + wt];
        }

        float cx = 0.f, cy = 0.f, cz = 0.f;
        if (wt < 32) {
            const float* cp = g_xT + ((size_t)b * NN + idxc[wt]) * 3;
            cx = cp[0]; cy = cp[1]; cz = cp[2];
        }

        // feature gather -> u_F (shuffled rows 0,1 mod 4), packed neighbor pairs
        #pragma unroll
        for (int it = 0; it < 8; it++) {
            int e = wt + it * 128;
            int c = e & 63, k2 = e >> 6;
            float f0 = g_featT[((size_t)b * NN + idxc[2 * k2])     * CIN + c];
            float f1 = g_featT[((size_t)b * NN + idxc[2 * k2 + 1]) * CIN + c];
            u_F[wg][(c & 31) * 4 + (c >> 5)][k2] = pack2(f0, f1);
        }

        if (wt < 32) {
            float c0x = __shfl_sync(0xffffffffu, cx, 0);
            float c0y = __shfl_sync(0xffffffffu, cy, 0);
            float c0z = __shfl_sync(0xffffffffu, cz, 0);
            float rx = cx - c0x, ry = cy - c0y, rz = cz - c0z;
            s_rel[wg][wt][0] = rx; s_rel[wg][wt][1] = ry; s_rel[wg][wt][2] = rz;
            s_dis[wg][wt] = sqrtf(rx * rx + ry * ry + rz * rz);
            s_base[wg][wt] = c0x * s_br[0][wt] + c0y * s_br[1][wt] + c0z * s_br[2][wt];
        }
        __syncthreads();

        // ---- RFF: sin/cos pairs -> u_xf ----
        #pragma unroll
        for (int it = 0; it < 4; it++) {
            int e = wt + it * 128;
            int k = e >> 4, m2 = e & 15;
            float rx = s_rel[wg][k][0], ry = s_rel[wg][k][1], rz = s_rel[wg][k][2];
            float dd = s_dis[wg][k];
            int m = 2 * m2;
            float t0 = s_base[wg][m]   + rx * s_br[3][m]   + ry * s_br[4][m]
                     + rz * s_br[5][m]   + dd * s_br[6][m];
            float t1 = s_base[wg][m+1] + rx * s_br[3][m+1] + ry * s_br[4][m+1]
                     + rz * s_br[5][m+1] + dd * s_br[6][m+1];
            float s0, cv0, s1, cv1;
            __sincosf(t0, &s0, &cv0);
            __sincosf(t1, &s1, &cv1);
            u_xf[wg][k][m2]      = pack2(s0, s1);
            u_xf[wg][k][16 + m2] = pack2(cv0, cv1);
        }

        // ---- topkmax (col j, row-quarter q), dots held in regs ----
        {
            const int j = wt & 31;
            const int q = wt >> 5;
            const float kx = s_kn[0][j], ky = s_kn[1][j], kz = s_kn[2][j];
            float d[8];
            float ps1 = 0.f;
            #pragma unroll
            for (int r = 0; r < 8; r++) {
                const int i = q * 8 + r;
                float v = s_rel[wg][i][0] * kx + s_rel[wg][i][1] * ky + s_rel[wg][i][2] * kz;
                if (i == 0 && j == 0) v += 1.0f;
                v = fmaxf(v, 0.f);
                d[r] = v;
                ps1 += v;
            }
            s_red[wg][q][j] = ps1;
            __syncthreads();
            float s1t = s_red[wg][0][j] + s_red[wg][1][j] + s_red[wg][2][j] + s_red[wg][3][j];
            float r1 = 1.0f / (s1t + 1e-6f);
            float ps2 = 0.f;
            #pragma unroll
            for (int r = 0; r < 8; r++) {
                float v = d[r] * r1;
                d[r] = v;
                ps2 += v * v;
            }
            __syncthreads();
            s_red[wg][q][j] = ps2;
            __syncthreads();
            float s2t = s_red[wg][0][j] + s_red[wg][1][j] + s_red[wg][2][j] + s_red[wg][3][j];
            float r2 = 1.0f / (s2t + 1e-6f);
            #pragma unroll
            for (int rp = 0; rp < 4; rp++) {
                float v0 = d[2 * rp]     * d[2 * rp]     * r2;
                float v1 = d[2 * rp + 1] * d[2 * rp + 1] * r2;
                v0 = (v0 > 0.1f) ? v0 : 0.0f;
                v1 = (v1 > 0.1f) ? v1 : 0.0f;
                u_pT[wg][j][4 * q + rp] = pack2(v0, v1);
            }
        }
        __syncthreads();

        // ---- GEMM1: mlp out rows [16w,16w+16), B via ldmatrix ----
        {
            float acc[4][4];
            #pragma unroll
            for (int nt = 0; nt < 4; nt++) {
                acc[nt][0] = bv0; acc[nt][1] = bv0;
                acc[nt][2] = bv1; acc[nt][3] = bv1;
            }
            #pragma unroll
            for (int nt = 0; nt < 4; nt++) {
                unsigned bx[2][4];
                #pragma unroll
                for (int win = 0; win < 2; win++)
                    ldsm4(bx[win][0], bx[win][1], bx[win][2], bx[win][3],
                          xfb + (nt * 8 + lrow8) * 144 + win * 64 + l3 * 16);
                #pragma unroll
                for (int ks = 0; ks < 4; ks++)
                    mma_f16(acc[nt][0], acc[nt][1], acc[nt][2], acc[nt][3],
                            amw[ks][0], amw[ks][1], amw[ks][2], amw[ks][3],
                            bx[ks >> 1][(ks & 1) * 2], bx[ks >> 1][(ks & 1) * 2 + 1]);
            }
            const int r0 = w * 16 + grp, r1 = r0 + 8;
            const int cs0 = (r0 & 31) * 4 + 2 + (r0 >> 5);
            const int cs1 = (r1 & 31) * 4 + 2 + (r1 >> 5);
            #pragma unroll
            for (int nt = 0; nt < 4; nt++) {
                u_F[wg][cs0][nt * 4 + tig] = pack2(acc[nt][0], acc[nt][1]);
                u_F[wg][cs1][nt * 4 + tig] = pack2(acc[nt][2], acc[nt][3]);
            }
        }
        __syncthreads();

        // ---- GEMM2: feats2 = F @ perm, A/B via ldmatrix ----
        {
            float acc[2][4][4];
            #pragma unroll
            for (int mt = 0; mt < 2; mt++)
                #pragma unroll
                for (int nt = 0; nt < 4; nt++)
                    #pragma unroll
                    for (int r = 0; r < 4; r++) acc[mt][nt][r] = 0.f;

            unsigned a[2][2][4];
            #pragma unroll
            for (int ks = 0; ks < 2; ks++)
                #pragma unroll
                for (int mt = 0; mt < 2; mt++) {
                    int row = w * 32 + mt * 16 + lrow8 + lhi * 8;
                    ldsm4(a[ks][mt][0], a[ks][mt][1], a[ks][mt][2], a[ks][mt][3],
                          fb + row * 80 + ks * 32 + lcol * 16);
                }
            unsigned bp[4][4];
            #pragma unroll
            for (int nt = 0; nt < 4; nt++)
                ldsm4(bp[nt][0], bp[nt][1], bp[nt][2], bp[nt][3],
                      ptb + (nt * 8 + lrow8) * 80 + l3 * 16);

            #pragma unroll
            for (int ks = 0; ks < 2; ks++)
                #pragma unroll
                for (int nt = 0; nt < 4; nt++)
                    #pragma unroll
                    for (int mt = 0; mt < 2; mt++)
                        mma_f16(acc[mt][nt][0], acc[mt][nt][1], acc[mt][nt][2], acc[mt][nt][3],
                                a[ks][mt][0], a[ks][mt][1], a[ks][mt][2], a[ks][mt][3],
                                bp[nt][2 * ks], bp[nt][2 * ks + 1]);

            // stage back into u_F in [row][k2] layout
            #pragma unroll
            for (int mt = 0; mt < 2; mt++) {
                const int r = w * 32 + mt * 16 + grp;
                #pragma unroll
                for (int nt = 0; nt < 4; nt++) {
                    u_F[wg][r][nt * 4 + tig]     = pack2(acc[mt][nt][0], acc[mt][nt][1]);
                    u_F[wg][r + 8][nt * 4 + tig] = pack2(acc[mt][nt][2], acc[mt][nt][3]);
                }
            }
        }
        __syncthreads();

        // ---- coalesced copy-out: u_F[wg] -> g_Ah[p] ----
        {
            unsigned* Ap = reinterpret_cast<unsigned*>(g_Ah + (size_t)p * KDIM);
            #pragma unroll
            for (int it = 0; it < 4; it++) {
                int e = wt + it * 128;
                int row = e >> 2;
                int c4 = (e & 3) * 4;
                uint4 v = *reinterpret_cast<const uint4*>(&u_F[wg][row][c4]);
                *reinterpret_cast<uint4*>(Ap + row * 16 + c4) = v;
            }
        }
        __syncthreads();   // protect u_F/u_xf/u_pT reuse + publish prefetched idx
    }
}

// ---------------- kernel 2: M-split gemm — 256 CTAs of 64m x 128n, cp.async 4-stage --
#define ROW_U 20
#define TM 64
#define A_ST_U (TM * ROW_U)
#define B_ST_U (128 * ROW_U)
#define STAGE_U (A_ST_U + B_ST_U)
#define NSTAGE 4
#define G_SMEM (NSTAGE * STAGE_U * 4)   // 61440 B
#define NIT 128

__global__ __launch_bounds__(256, 2) void gemm_kernel(
    const float* __restrict__ bias, float* __restrict__ out)
{
    extern __shared__ unsigned sm[];
    __shared__ float s_bias[COUT];

    const int t = threadIdx.x;
    const int p0 = blockIdx.x * TM;
    const int bb = p0 >> 11;
    const int n0 = p0 & (NN - 1);

    if (t < COUT) s_bias[t] = bias[t];

    const int lane = t & 31;
    const int wid  = t >> 5;
    const int grp  = lane >> 2;
    const int tig  = lane & 3;
    const int wm = (wid & 1) * 32;
    const int wn = (wid >> 1) * 32;

    const unsigned* Ag = reinterpret_cast<const unsigned*>(g_Ah);
    const unsigned* Bg = g_cwP;
    const uint32_t smb = smem_u32(sm);

    const int srow = t >> 2;
    const int sch  = t & 3;

    auto issue = [&](int q, int slot) {
        const uint32_t sb = smb + slot * (STAGE_U * 4);
        cp16(sb + srow * 80 + sch * 16,
             Ag + (size_t)(p0 + srow) * KD2 + q * 16 + sch * 4);
        #pragma unroll
        for (int i = 0; i < 2; i++) {
            int o = srow + 64 * i;
            cp16(sb + A_ST_U * 4 + o * 80 + sch * 16,
                 Bg + (size_t)o * KD2 + q * 16 + sch * 4);
        }
        cp_commit();
    };

    float c[2][4][4];
    #pragma unroll
    for (int ma = 0; ma < 2; ma++)
        #pragma unroll
        for (int nb = 0; nb < 4; nb++)
            #pragma unroll
            for (int r = 0; r < 4; r++) c[ma][nb][r] = 0.f;

    issue(0, 0);
    issue(1, 1);
    issue(2, 2);

    const int lrow8 = lane & 7;
    const int lhi   = (lane >> 3) & 1;
    const int lcol  = (lane >> 4) & 1;

    for (int i = 0; i < NIT; i++) {
        cp_wait<2>();
        __syncthreads();
        if (i + 3 < NIT) issue(i + 3, (i + 3) & 3);

        const uint32_t ab = smb + (i & 3) * (STAGE_U * 4);
        const uint32_t bbod = ab + A_ST_U * 4;

        unsigned a[2][2][4];
        #pragma unroll
        for (int ks = 0; ks < 2; ks++)
            #pragma unroll
            for (int ma = 0; ma < 2; ma++) {
                int row = wm + ma * 16 + lrow8 + lhi * 8;
                uint32_t addr = ab + row * 80 + ks * 32 + lcol * 16;
                ldsm4(a[ks][ma][0], a[ks][ma][1], a[ks][ma][2], a[ks][ma][3], addr);
            }
        unsigned bf[4][4];
        {
            const int bcol = (lane >> 3) * 16;
            #pragma unroll
            for (int nb = 0; nb < 4; nb++) {
                int row = wn + nb * 8 + lrow8;
                ldsm4(bf[nb][0], bf[nb][1], bf[nb][2], bf[nb][3],
                      bbod + row * 80 + bcol);
            }
        }
        #pragma unroll
        for (int ks = 0; ks < 2; ks++)
            #pragma unroll
            for (int nb = 0; nb < 4; nb++)
                #pragma unroll
                for (int ma = 0; ma < 2; ma++)
                    mma_f16(c[ma][nb][0], c[ma][nb][1], c[ma][nb][2], c[ma][nb][3],
                            a[ks][ma][0], a[ks][ma][1], a[ks][ma][2], a[ks][ma][3],
                            bf[nb][2 * ks], bf[nb][2 * ks + 1]);
    }

    float* ob = out + (size_t)bb * COUT * NN;
    #pragma unroll
    for (int ma = 0; ma < 2; ma++) {
        const int m0 = wm + ma * 16 + grp;
        #pragma unroll
        for (int nb = 0; nb < 4; nb++) {
            const int col0 = wn + nb * 8 + tig * 2;
            const float bv0 = s_bias[col0], bv1 = s_bias[col0 + 1];
            ob[(size_t)col0       * NN + n0 + m0]     = c[ma][nb][0] + bv0;
            ob[(size_t)(col0 + 1) * NN + n0 + m0]     = c[ma][nb][1] + bv1;
            ob[(size_t)col0       * NN + n0 + m0 + 8] = c[ma][nb][2] + bv0;
            ob[(size_t)(col0 + 1) * NN + n0 + m0 + 8] = c[ma][nb][3] + bv1;
        }
    }
}

// ---------------- launch ----------------
extern "C" void kernel_launch(void* const* d_in, const int* in_sizes, int n_in,
                              void* d_out, int out_size) {
    const float* x       = (const float*)d_in[0];
    const float* feature = (const float*)d_in[1];
    const int*   nidx    = (const int*)  d_in[2];
    const float* Brff    = (const float*)d_in[3];
    const float* kern    = (const float*)d_in[4];
    const float* mw      = (const float*)d_in[5];
    const float* mb      = (const float*)d_in[6];
    const float* cw      = (const float*)d_in[7];
    const float* cb      = (const float*)d_in[8];
    float* out = (float*)d_out;

    cudaFuncSetAttribute(gemm_kernel,
                         cudaFuncAttributeMaxDynamicSharedMemorySize, G_SMEM);

    prep_kernel<<<1024, 256>>>(x, feature, cw, mw);
    point_kernel<<<PGRID, 256>>>(nidx, Brff, kern, mb);
    gemm_kernel<<<NPTS / TM, 256, G_SMEM>>>(cb, out);
}